// round 15
// baseline (speedup 1.0000x reference)
#include <cuda_runtime.h>
#include <cuda_bf16.h>
#include <cuda_fp16.h>
#include <cuda_fp8.h>
#include <cstdint>
#include <cstddef>

// Problem dims (fixed by the dataset)
#define MDIM 8192
#define KDIM 4096
#define NDIM 4096
#define QBLOCK 128
#define FP8_MAX_F 448.0f
#define KBLOCKS (KDIM / QBLOCK)   // 32

// GEMM tiling: CTA 128x128x64(fp8), 16 warps as 4(m) x 4(n), warp tile 32x32
#define BM 128
#define BN 128
#define BK 64
#define KTILES (KDIM / BK)        // 64
#define STAGES 4
#define NTHREADS 512
#define LDAB 80                   // 64B fp8 row + 16B pad (conflict-free ldmatrix)
#define A_BYTES (BM * LDAB)       // 10240
#define B_BYTES (BN * LDAB)       // 10240
#define STAGE_BYTES (A_BYTES + B_BYTES)      // 20480
#define SMEM_DYN (STAGES * STAGE_BYTES)      // 81920

// fused quant kernel split
#define QX_BLOCKS ((MDIM * KBLOCKS) / 8)       // 32768 (8 warps/CTA, warp per block)
#define QW_BLOCKS ((NDIM * KDIM) / 8 / 256)    // 8192  (8 elems/thread)

// Scratch (device globals; no runtime allocation)
__device__ __align__(16) uint8_t g_A[(size_t)MDIM * KDIM];    // 32 MB, [M][K]
__device__ __align__(16) uint8_t g_B[(size_t)NDIM * KDIM];    // 16 MB, [N][K]
__device__ __align__(16) float   g_Sx[(size_t)MDIM * KBLOCKS]; // 1 MB, [M][Kb]

// ---------------------------------------------------------------------------
// helpers
// ---------------------------------------------------------------------------
__device__ __forceinline__ void cp_async16(uint32_t smem_dst, const void* gptr) {
    asm volatile("cp.async.cg.shared.global [%0], [%1], 16;"
                 :: "r"(smem_dst), "l"(gptr) : "memory");
}

__device__ __forceinline__ void ldmatrix_x4(uint32_t* r, uint32_t addr) {
    asm volatile("ldmatrix.sync.aligned.m8n8.x4.shared.b16 {%0,%1,%2,%3}, [%4];"
                 : "=r"(r[0]), "=r"(r[1]), "=r"(r[2]), "=r"(r[3])
                 : "r"(addr) : "memory");
}

// fp8 e4m3 MMA: m16n8k32, f32 accumulate (sm_89+ baseline feature)
__device__ __forceinline__ void mma_fp8(float* c, const uint32_t* a,
                                        const uint32_t* b) {
    asm volatile(
        "mma.sync.aligned.m16n8k32.row.col.f32.e4m3.e4m3.f32 "
        "{%0,%1,%2,%3}, {%4,%5,%6,%7}, {%8,%9}, {%0,%1,%2,%3};"
        : "+f"(c[0]), "+f"(c[1]), "+f"(c[2]), "+f"(c[3])
        : "r"(a[0]), "r"(a[1]), "r"(a[2]), "r"(a[3]), "r"(b[0]), "r"(b[1]));
}

// packed e4m3x2 convert (RN, satfinite) — low byte = .x, high byte = .y
__device__ __forceinline__ uint32_t fp8x4(float a, float b, float c, float d) {
    __nv_fp8x2_storage_t lo = __nv_cvt_float2_to_fp8x2(make_float2(a, b),
                                                       __NV_SATFINITE, __NV_E4M3);
    __nv_fp8x2_storage_t hi = __nv_cvt_float2_to_fp8x2(make_float2(c, d),
                                                       __NV_SATFINITE, __NV_E4M3);
    return (uint32_t)lo | ((uint32_t)hi << 16);
}

// ---------------------------------------------------------------------------
// Kernel 1 (fused): activation blockwise fp8 quantize + weight fp8 cast
// ---------------------------------------------------------------------------
__global__ void __launch_bounds__(256) quant_fused_kernel(const float* __restrict__ x,
                                                          const float* __restrict__ w) {
    if (blockIdx.x < QX_BLOCKS) {
        int wg = (blockIdx.x * 256 + threadIdx.x) >> 5;  // block index = m*32+kb
        int lane = threadIdx.x & 31;
        size_t base = (size_t)wg * QBLOCK;
        float4 v = reinterpret_cast<const float4*>(x + base)[lane];

        float amax = fmaxf(fmaxf(fabsf(v.x), fabsf(v.y)),
                           fmaxf(fabsf(v.z), fabsf(v.w)));
        #pragma unroll
        for (int off = 16; off > 0; off >>= 1)
            amax = fmaxf(amax, __shfl_xor_sync(0xffffffffu, amax, off));
        float scale = fmaxf(amax, 1e-12f) / FP8_MAX_F;
        float inv = 1.0f / scale;

        uint32_t p = fp8x4(v.x * inv, v.y * inv, v.z * inv, v.w * inv);
        reinterpret_cast<uint32_t*>(g_A)[(size_t)wg * 32 + lane] = p;

        if (lane == 0) g_Sx[wg] = scale;  // layout [m][kb] == linear wg
    } else {
        size_t i = ((size_t)(blockIdx.x - QX_BLOCKS) * 256 + threadIdx.x) * 8;
        float4 v0 = *reinterpret_cast<const float4*>(w + i);
        float4 v1 = *reinterpret_cast<const float4*>(w + i + 4);
        uint2 p;
        p.x = fp8x4(v0.x, v0.y, v0.z, v0.w);
        p.y = fp8x4(v1.x, v1.y, v1.z, v1.w);
        *reinterpret_cast<uint2*>(g_B + i) = p;
    }
}

// ---------------------------------------------------------------------------
// Kernel 2: fp8 mma.sync GEMM, 512 threads (16 warps, 4x4), warp tile 32x32
//   Horner per-128k-block rescale; 2 CTAs/SM target (occ 50%)
// ---------------------------------------------------------------------------
__global__ void __launch_bounds__(NTHREADS, 2) gemm_kernel(const float* __restrict__ wsinv,
                                                           const float* __restrict__ bias,
                                                           float* __restrict__ out) {
    extern __shared__ uint8_t smem[];
    __shared__ float bias_s[BN];
    __shared__ float ratio_s[KBLOCKS * BM];  // [kb][m_local], 16KB

    const int tid = threadIdx.x;
    const int wid = tid >> 5;
    const int lane = tid & 31;
    const int warp_m = wid & 3;   // 0..3 -> m rows 32*warp_m
    const int warp_n = wid >> 2;  // 0..3 -> n cols 32*warp_n

    // n-major rasterization: consecutive CTAs share the A band, B stays in L2
    const int n_tile = blockIdx.x & ((NDIM / BN) - 1);
    const int m_tile = blockIdx.x >> 5;
    const int m0 = m_tile * BM;
    const int n0 = n_tile * BN;
    const int nb = n0 >> 7;       // weight n-block (BN == QBLOCK)

    if (tid < BN)
        bias_s[tid] = __bfloat162float(__float2bfloat16_rn(bias[n0 + tid]));
    // ratio table: ratio[kb][m] = f(m,kb)/f(m,kb+1) for kb<31; ratio[31][m] = f(m,31)
    #pragma unroll
    for (int idx = tid; idx < KBLOCKS * BM; idx += NTHREADS) {
        int m = idx >> 5, kb = idx & (KBLOCKS - 1);
        const float* sxp = g_Sx + (size_t)(m0 + m) * KBLOCKS;
        float f0 = wsinv[nb * KBLOCKS + kb] * sxp[kb];
        float r;
        if (kb < KBLOCKS - 1) {
            float f1 = wsinv[nb * KBLOCKS + kb + 1] * sxp[kb + 1];
            r = f0 / f1;
        } else {
            r = f0;
        }
        ratio_s[kb * BM + m] = r;
    }
    __syncthreads();

    const uint32_t smem_u32 = (uint32_t)__cvta_generic_to_shared(smem);

    // ---- cp.async: 512 threads cover each 128x64 operand exactly once ----
    const int cp_row = tid >> 2;            // 0..127
    const int cp_c0 = (tid & 3) * 16;
    const uint32_t aSm = cp_row * LDAB + cp_c0;
    const uint32_t bSm = A_BYTES + aSm;
    const uint8_t* aG = g_A + (size_t)(m0 + cp_row) * KDIM + cp_c0;
    const uint8_t* bG = g_B + (size_t)(n0 + cp_row) * KDIM + cp_c0;

    auto issue_stage = [&](uint32_t stage_base) {
        cp_async16(stage_base + aSm, aG);
        cp_async16(stage_base + bSm, bG);
        asm volatile("cp.async.commit_group;" ::: "memory");
        aG += BK; bG += BK;
    };

    // ---- precomputed ldmatrix offsets (stage-relative) ----
    uint32_t aOff[2], bOff[2];
    #pragma unroll
    for (int mf = 0; mf < 2; mf++)
        aOff[mf] = (uint32_t)((warp_m * 32 + mf * 16 + (lane & 15)) * LDAB +
                              (lane >> 4) * 16);
    #pragma unroll
    for (int p = 0; p < 2; p++)
        bOff[p] = (uint32_t)(A_BYTES +
                             (warp_n * 32 + p * 16 + (lane >> 4) * 8 + (lane & 7)) * LDAB +
                             ((lane >> 3) & 1) * 16);

    float acc[2][4][4];   // [mf][nf][frag] — single Horner accumulator (32 regs)
    #pragma unroll
    for (int mf = 0; mf < 2; mf++)
        #pragma unroll
        for (int nf = 0; nf < 4; nf++)
            #pragma unroll
            for (int j = 0; j < 4; j++) acc[mf][nf][j] = 0.f;

    issue_stage(smem_u32 + 0 * STAGE_BYTES);
    issue_stage(smem_u32 + 1 * STAGE_BYTES);
    issue_stage(smem_u32 + 2 * STAGE_BYTES);

    const int qrow = lane >> 2;
    const int qcol = (lane & 3) * 2;
    const int rBase0 = warp_m * 32 + qrow;          // mf=0 row; mf=1 is +16

    const float* rp = ratio_s;   // advances BM per 128-k block boundary

    for (int kt0 = 0; kt0 < KTILES; kt0 += STAGES) {
        #pragma unroll
        for (int s = 0; s < STAGES; s++) {
            const int kt = kt0 + s;
            if (kt < KTILES - (STAGES - 1))
                asm volatile("cp.async.wait_group %0;" :: "n"(STAGES - 2) : "memory");
            else
                asm volatile("cp.async.wait_group 0;" ::: "memory");
            __syncthreads();

            if (kt + STAGES - 1 < KTILES)
                issue_stage(smem_u32 + ((s + STAGES - 1) & (STAGES - 1)) * STAGE_BYTES);

            const uint32_t stage_base = smem_u32 + s * STAGE_BYTES;

            #pragma unroll
            for (int ks = 0; ks < 2; ks++) {   // two k32 steps per BK=64
                const uint32_t kbyte = ks * 32;
                uint32_t a[2][4], b[2][4];
                #pragma unroll
                for (int mf = 0; mf < 2; mf++)
                    ldmatrix_x4(a[mf], stage_base + aOff[mf] + kbyte);
                #pragma unroll
                for (int p = 0; p < 2; p++)
                    ldmatrix_x4(b[p], stage_base + bOff[p] + kbyte);
                #pragma unroll
                for (int mf = 0; mf < 2; mf++)
                    #pragma unroll
                    for (int nf = 0; nf < 4; nf++)
                        mma_fp8(acc[mf][nf], a[mf], &b[nf >> 1][(nf & 1) * 2]);
            }

            if (s & 1) {  // kt odd: block boundary — Horner multiply (telescoping)
                #pragma unroll
                for (int mf = 0; mf < 2; mf++) {
                    float f0 = rp[rBase0 + mf * 16];
                    float f1 = rp[rBase0 + mf * 16 + 8];
                    #pragma unroll
                    for (int nf = 0; nf < 4; nf++) {
                        acc[mf][nf][0] *= f0;
                        acc[mf][nf][1] *= f0;
                        acc[mf][nf][2] *= f1;
                        acc[mf][nf][3] *= f1;
                    }
                }
                rp += BM;
            }
        }
    }

    // Epilogue: bf16(y) + bf16(bias), f32 add, round to bf16, upcast to f32
    #pragma unroll
    for (int mf = 0; mf < 2; mf++) {
        #pragma unroll
        for (int nf = 0; nf < 4; nf++) {
            int cn = warp_n * 32 + nf * 8 + qcol;
            float b0 = bias_s[cn], b1 = bias_s[cn + 1];
            #pragma unroll
            for (int half = 0; half < 2; half++) {
                int m = m0 + warp_m * 32 + mf * 16 + qrow + half * 8;
                float y0 = acc[mf][nf][half * 2 + 0];
                float y1 = acc[mf][nf][half * 2 + 1];
                float v0 = __bfloat162float(__float2bfloat16_rn(y0)) + b0;
                float v1 = __bfloat162float(__float2bfloat16_rn(y1)) + b1;
                float2 o;
                o.x = __bfloat162float(__float2bfloat16_rn(v0));
                o.y = __bfloat162float(__float2bfloat16_rn(v1));
                *reinterpret_cast<float2*>(out + (size_t)m * NDIM + n0 + cn) = o;
            }
        }
    }
}

// ---------------------------------------------------------------------------
// launch — inputs resolved by element count (robust to metadata ordering)
// ---------------------------------------------------------------------------
extern "C" void kernel_launch(void* const* d_in, const int* in_sizes, int n_in,
                              void* d_out, int out_size) {
    (void)out_size;
    const float *x = nullptr, *w = nullptr, *wsinv = nullptr, *bias = nullptr;
    for (int i = 0; i < n_in; i++) {
        switch (in_sizes[i]) {
            case MDIM * KDIM:                 x     = (const float*)d_in[i]; break; // 33554432
            case NDIM * KDIM:                 w     = (const float*)d_in[i]; break; // 16777216
            case (NDIM/QBLOCK)*(KDIM/QBLOCK): wsinv = (const float*)d_in[i]; break; // 1024
            case NDIM:                        bias  = (const float*)d_in[i]; break; // 4096
        }
    }
    float* out = (float*)d_out;

    {
        quant_fused_kernel<<<QX_BLOCKS + QW_BLOCKS, 256>>>(x, w);
    }
    {
        cudaFuncSetAttribute(gemm_kernel,
                             cudaFuncAttributeMaxDynamicSharedMemorySize, SMEM_DYN);
        dim3 grid((MDIM / BM) * (NDIM / BN));  // 2048
        gemm_kernel<<<grid, NTHREADS, SMEM_DYN>>>(wsinv, bias, out);
    }
}

// round 16
// speedup vs baseline: 1.4669x; 1.4669x over previous
#include <cuda_runtime.h>
#include <cuda_bf16.h>
#include <cuda_fp16.h>
#include <cuda_fp8.h>
#include <cstdint>
#include <cstddef>

// Problem dims (fixed by the dataset)
#define MDIM 8192
#define KDIM 4096
#define NDIM 4096
#define QBLOCK 128
#define FP8_MAX_F 448.0f
#define KBLOCKS (KDIM / QBLOCK)   // 32

// GEMM tiling: CTA 128x128x128(fp8), 8 warps as 2(m) x 4(n), warp tile 64x32
#define BM 128
#define BN 128
#define BK 128
#define KTILES (KDIM / BK)        // 32
#define STAGES 3
#define NTHREADS 256
#define LDAB 128                  // swizzled rows (chunk ^= row&7), no pad
#define A_BYTES (BM * LDAB)       // 16384
#define B_BYTES (BN * LDAB)       // 16384
#define RX_OFF (A_BYTES + B_BYTES)          // 32768
#define RX_BYTES 512
#define STAGE_BYTES (RX_OFF + RX_BYTES)     // 33280 (multiple of 128)
#define SMEM_DYN (STAGES * STAGE_BYTES + 128) // + align slack

// fused quant kernel split
#define QX_BLOCKS ((MDIM * KBLOCKS) / 8)       // 32768
#define QW_BLOCKS ((NDIM * KDIM) / 8 / 256)    // 8192

// Scratch (device globals; no runtime allocation)
__device__ __align__(16) uint8_t g_A[(size_t)MDIM * KDIM];     // 32 MB, [M][K]
__device__ __align__(16) uint8_t g_B[(size_t)NDIM * KDIM];     // 16 MB, [N][K]
__device__ __align__(16) float   g_Sx[(size_t)MDIM * KBLOCKS]; // 1 MB, [M][Kb]
__device__ __align__(16) float   g_Rx[(size_t)KBLOCKS * MDIM]; // 1 MB, [Kb][M]

// ---------------------------------------------------------------------------
// helpers
// ---------------------------------------------------------------------------
__device__ __forceinline__ void cp_async16(uint32_t smem_dst, const void* gptr) {
    asm volatile("cp.async.cg.shared.global [%0], [%1], 16;"
                 :: "r"(smem_dst), "l"(gptr) : "memory");
}

__device__ __forceinline__ void ldmatrix_x4(uint32_t* r, uint32_t addr) {
    asm volatile("ldmatrix.sync.aligned.m8n8.x4.shared.b16 {%0,%1,%2,%3}, [%4];"
                 : "=r"(r[0]), "=r"(r[1]), "=r"(r[2]), "=r"(r[3])
                 : "r"(addr) : "memory");
}

// fp8 e4m3 MMA: m16n8k32, f32 accumulate (sm_89+ baseline feature)
__device__ __forceinline__ void mma_fp8(float* c, const uint32_t* a,
                                        const uint32_t* b) {
    asm volatile(
        "mma.sync.aligned.m16n8k32.row.col.f32.e4m3.e4m3.f32 "
        "{%0,%1,%2,%3}, {%4,%5,%6,%7}, {%8,%9}, {%0,%1,%2,%3};"
        : "+f"(c[0]), "+f"(c[1]), "+f"(c[2]), "+f"(c[3])
        : "r"(a[0]), "r"(a[1]), "r"(a[2]), "r"(a[3]), "r"(b[0]), "r"(b[1]));
}

__device__ __forceinline__ float lds_f32(uint32_t addr) {
    float v;
    asm volatile("ld.shared.f32 %0, [%1];" : "=f"(v) : "r"(addr));
    return v;
}

// packed e4m3x2 convert (RN, satfinite) — low byte = .x, high byte = .y
__device__ __forceinline__ uint32_t fp8x4(float a, float b, float c, float d) {
    __nv_fp8x2_storage_t lo = __nv_cvt_float2_to_fp8x2(make_float2(a, b),
                                                       __NV_SATFINITE, __NV_E4M3);
    __nv_fp8x2_storage_t hi = __nv_cvt_float2_to_fp8x2(make_float2(c, d),
                                                       __NV_SATFINITE, __NV_E4M3);
    return (uint32_t)lo | ((uint32_t)hi << 16);
}

// ---------------------------------------------------------------------------
// Kernel 1 (fused): activation blockwise fp8 quantize + weight fp8 cast
// ---------------------------------------------------------------------------
__global__ void __launch_bounds__(256) quant_fused_kernel(const float* __restrict__ x,
                                                          const float* __restrict__ w) {
    if (blockIdx.x < QX_BLOCKS) {
        int wg = (blockIdx.x * 256 + threadIdx.x) >> 5;  // block index = m*32+kb
        int lane = threadIdx.x & 31;
        size_t base = (size_t)wg * QBLOCK;
        float4 v = reinterpret_cast<const float4*>(x + base)[lane];

        float amax = fmaxf(fmaxf(fabsf(v.x), fabsf(v.y)),
                           fmaxf(fabsf(v.z), fabsf(v.w)));
        #pragma unroll
        for (int off = 16; off > 0; off >>= 1)
            amax = fmaxf(amax, __shfl_xor_sync(0xffffffffu, amax, off));
        float scale = fmaxf(amax, 1e-12f) / FP8_MAX_F;
        float inv = 1.0f / scale;

        uint32_t p = fp8x4(v.x * inv, v.y * inv, v.z * inv, v.w * inv);
        reinterpret_cast<uint32_t*>(g_A)[(size_t)wg * 32 + lane] = p;

        if (lane == 0) g_Sx[wg] = scale;  // layout [m][kb] == linear wg
    } else {
        size_t i = ((size_t)(blockIdx.x - QX_BLOCKS) * 256 + threadIdx.x) * 8;
        float4 v0 = *reinterpret_cast<const float4*>(w + i);
        float4 v1 = *reinterpret_cast<const float4*>(w + i + 4);
        uint2 p;
        p.x = fp8x4(v0.x, v0.y, v0.z, v0.w);
        p.y = fp8x4(v1.x, v1.y, v1.z, v1.w);
        *reinterpret_cast<uint2*>(g_B + i) = p;
    }
}

// ---------------------------------------------------------------------------
// Kernel 2: activation-scale ratio table  rx[kb][m]
//   kb<31: sx(m,kb)/sx(m,kb+1);  kb=31: sx(m,31)
// ---------------------------------------------------------------------------
__global__ void __launch_bounds__(256) rx_kernel() {
    int idx = blockIdx.x * 256 + threadIdx.x;      // kb*8192 + m
    int kb = idx >> 13;
    int m = idx & (MDIM - 1);
    float s0 = g_Sx[(size_t)m * KBLOCKS + kb];
    float r = (kb < KBLOCKS - 1) ? s0 / g_Sx[(size_t)m * KBLOCKS + kb + 1] : s0;
    g_Rx[idx] = r;
}

// ---------------------------------------------------------------------------
// Kernel 3: fp8 mma.sync GEMM, BK=128, 3 swizzled stages, Horner rescale
//   y[m,n] = sum_kb f(m,kb)*S_kb;  acc *= rw(kb)*rx(m,kb) each iteration
// ---------------------------------------------------------------------------
__global__ void __launch_bounds__(NTHREADS, 2) gemm_kernel(const float* __restrict__ wsinv,
                                                           const float* __restrict__ bias,
                                                           float* __restrict__ out) {
    extern __shared__ __align__(128) uint8_t smem_raw[];
    __shared__ float bias_s[BN];
    __shared__ float rw_s[KBLOCKS];

    const int tid = threadIdx.x;
    const int wid = tid >> 5;
    const int lane = tid & 31;
    const int warp_m = wid & 1;   // 0..1 -> m rows 64*warp_m
    const int warp_n = wid >> 1;  // 0..3 -> n cols 32*warp_n

    // n-major rasterization: consecutive CTAs share the A band, B stays in L2
    const int n_tile = blockIdx.x & ((NDIM / BN) - 1);
    const int m_tile = blockIdx.x >> 5;
    const int m0 = m_tile * BM;
    const int n0 = n_tile * BN;
    const int nb = n0 >> 7;       // weight n-block (BN == QBLOCK)

    if (tid < BN)
        bias_s[tid] = __bfloat162float(__float2bfloat16_rn(bias[n0 + tid]));
    if (tid < KBLOCKS) {          // weight-scale ratio row
        float w0 = wsinv[nb * KBLOCKS + tid];
        rw_s[tid] = (tid < KBLOCKS - 1) ? w0 / wsinv[nb * KBLOCKS + tid + 1] : w0;
    }

    uint32_t smem_u32 = (uint32_t)__cvta_generic_to_shared(smem_raw);
    smem_u32 = (smem_u32 + 127u) & ~127u;   // 128B-align for swizzle

    // ---- cp.async: per stage, thread covers 4 A chunks + 4 B chunks (+rx) ----
    const int cp_row = tid >> 3;            // 0..31 (+32i)
    const int cp_c = tid & 7;               // 16B chunk col
    const uint32_t cp_sw = (uint32_t)(cp_c ^ (cp_row & 7)) << 4;
    const uint32_t dstA0 = cp_row * LDAB + cp_sw;            // +4096*i
    const uint32_t dstB0 = A_BYTES + dstA0;
    const uint8_t* aG = g_A + (size_t)(m0 + cp_row) * KDIM + cp_c * 16;
    const uint8_t* bG = g_B + (size_t)(n0 + cp_row) * KDIM + cp_c * 16;
    const float* rxG = g_Rx + m0 + tid * 4;  // advances +MDIM per stage

    auto issue_stage = [&](uint32_t sb) {
        #pragma unroll
        for (int i = 0; i < 4; i++) {
            cp_async16(sb + dstA0 + i * 32 * LDAB, aG + (size_t)i * 32 * KDIM);
            cp_async16(sb + dstB0 + i * 32 * LDAB, bG + (size_t)i * 32 * KDIM);
        }
        if (tid < 32) cp_async16(sb + RX_OFF + tid * 16, rxG);
        asm volatile("cp.async.commit_group;" ::: "memory");
        aG += BK; bG += BK; rxG += MDIM;
    };

    // ---- ldmatrix per-thread constants (swizzle split: base + xor) ----
    const int aHi = lane >> 4;               // A chunk half
    const int bHi = (lane >> 3) & 1;         // B chunk half
    uint32_t aBase[2], bBase[2];
    uint32_t aX7[2], bX7[2];
    #pragma unroll
    for (int mf2 = 0; mf2 < 2; mf2++) {      // A rows for mf = mf2 and mf2+2
        int row = warp_m * 64 + mf2 * 16 + (lane & 15);
        aBase[mf2] = row * LDAB; aX7[mf2] = row & 7;
    }
    #pragma unroll
    for (int p = 0; p < 2; p++) {
        int row = warp_n * 32 + p * 16 + ((lane >> 4) << 3) + (lane & 7);
        bBase[p] = A_BYTES + row * LDAB; bX7[p] = row & 7;
    }
    // mf=2,3 rows are mf=0,1 rows +32 -> same &7, +32*LDAB base

    float acc[4][4][4];   // [mf][nf][frag] — single Horner accumulator
    #pragma unroll
    for (int mf = 0; mf < 4; mf++)
        #pragma unroll
        for (int nf = 0; nf < 4; nf++)
            #pragma unroll
            for (int j = 0; j < 4; j++) acc[mf][nf][j] = 0.f;

    uint32_t cur = smem_u32;
    uint32_t nxt = smem_u32 + STAGE_BYTES;
    uint32_t prv = smem_u32 + 2 * STAGE_BYTES;

    __syncthreads();              // rw_s/bias_s ready (also orders nothing else)
    issue_stage(cur);
    issue_stage(nxt);

    const int qrow = lane >> 2;
    const int qcol = (lane & 3) * 2;
    uint32_t rxAddr[4];           // smem offsets (stage-relative) of ratio rows
    #pragma unroll
    for (int mf = 0; mf < 4; mf++)
        rxAddr[mf] = RX_OFF + (uint32_t)(warp_m * 64 + mf * 16 + qrow) * 4;

    for (int kt = 0; kt < KTILES; kt++) {
        if (kt < KTILES - 1)
            asm volatile("cp.async.wait_group 1;" ::: "memory");
        else
            asm volatile("cp.async.wait_group 0;" ::: "memory");
        __syncthreads();

        if (kt + 2 < KTILES) issue_stage(prv);

        #pragma unroll
        for (int ks = 0; ks < 4; ks++) {     // four k32 steps per BK=128
            uint32_t a[4][4], b[2][4];
            const uint32_t cA = ks * 2 + aHi;
            const uint32_t cB = ks * 2 + bHi;
            #pragma unroll
            for (int mf = 0; mf < 4; mf++) {
                int mf2 = mf & 1;
                uint32_t base = aBase[mf2] + (mf >> 1) * 32 * LDAB;
                ldmatrix_x4(a[mf], cur + base + ((cA ^ aX7[mf2]) << 4));
            }
            #pragma unroll
            for (int p = 0; p < 2; p++)
                ldmatrix_x4(b[p], cur + bBase[p] + ((cB ^ bX7[p]) << 4));
            #pragma unroll
            for (int mf = 0; mf < 4; mf++)
                #pragma unroll
                for (int nf = 0; nf < 4; nf++)
                    mma_fp8(acc[mf][nf], a[mf], &b[nf >> 1][(nf & 1) * 2]);
        }

        // Horner boundary every kt (BK == QBLOCK): acc *= rw(kb)*rx(m,kb)
        {
            const float rwv = rw_s[kt];
            #pragma unroll
            for (int mf = 0; mf < 4; mf++) {
                float f0 = rwv * lds_f32(cur + rxAddr[mf]);
                float f1 = rwv * lds_f32(cur + rxAddr[mf] + 32);
                #pragma unroll
                for (int nf = 0; nf < 4; nf++) {
                    acc[mf][nf][0] *= f0;
                    acc[mf][nf][1] *= f0;
                    acc[mf][nf][2] *= f1;
                    acc[mf][nf][3] *= f1;
                }
            }
        }

        uint32_t tmp = prv; prv = cur; cur = nxt; nxt = tmp;
    }

    // Epilogue: bf16(y) + bf16(bias), f32 add, round to bf16, upcast to f32
    #pragma unroll
    for (int mf = 0; mf < 4; mf++) {
        #pragma unroll
        for (int nf = 0; nf < 4; nf++) {
            int cn = warp_n * 32 + nf * 8 + qcol;
            float b0 = bias_s[cn], b1 = bias_s[cn + 1];
            #pragma unroll
            for (int half = 0; half < 2; half++) {
                int m = m0 + warp_m * 64 + mf * 16 + qrow + half * 8;
                float y0 = acc[mf][nf][half * 2 + 0];
                float y1 = acc[mf][nf][half * 2 + 1];
                float v0 = __bfloat162float(__float2bfloat16_rn(y0)) + b0;
                float v1 = __bfloat162float(__float2bfloat16_rn(y1)) + b1;
                float2 o;
                o.x = __bfloat162float(__float2bfloat16_rn(v0));
                o.y = __bfloat162float(__float2bfloat16_rn(v1));
                *reinterpret_cast<float2*>(out + (size_t)m * NDIM + n0 + cn) = o;
            }
        }
    }
}

// ---------------------------------------------------------------------------
// launch — inputs resolved by element count (robust to metadata ordering)
// ---------------------------------------------------------------------------
extern "C" void kernel_launch(void* const* d_in, const int* in_sizes, int n_in,
                              void* d_out, int out_size) {
    (void)out_size;
    const float *x = nullptr, *w = nullptr, *wsinv = nullptr, *bias = nullptr;
    for (int i = 0; i < n_in; i++) {
        switch (in_sizes[i]) {
            case MDIM * KDIM:                 x     = (const float*)d_in[i]; break; // 33554432
            case NDIM * KDIM:                 w     = (const float*)d_in[i]; break; // 16777216
            case (NDIM/QBLOCK)*(KDIM/QBLOCK): wsinv = (const float*)d_in[i]; break; // 1024
            case NDIM:                        bias  = (const float*)d_in[i]; break; // 4096
        }
    }
    float* out = (float*)d_out;

    quant_fused_kernel<<<QX_BLOCKS + QW_BLOCKS, 256>>>(x, w);
    rx_kernel<<<(KBLOCKS * MDIM) / 256, 256>>>();
    {
        cudaFuncSetAttribute(gemm_kernel,
                             cudaFuncAttributeMaxDynamicSharedMemorySize, SMEM_DYN);
        dim3 grid((MDIM / BM) * (NDIM / BN));  // 2048
        gemm_kernel<<<grid, NTHREADS, SMEM_DYN>>>(wsinv, bias, out);
    }
}